// round 1
// baseline (speedup 1.0000x reference)
#include <cuda_runtime.h>
#include <math.h>

#define SEQ 4096
#define EMB 1280
#define NH 16
#define HD 80
#define QKSCALE 8.94427190999915878564f  // sqrt(80) — reference MULTIPLIES by sqrt(head_dim)

// ---------------- device scratch (no allocations allowed) ----------------
__device__ float g_q[NH * SEQ * HD];     // [h][s][d]
__device__ float g_k[NH * SEQ * HD];
__device__ float g_v[NH * SEQ * HD];
__device__ float g_attn[SEQ * EMB];      // [s][h*80+d]

// ---------------- GEMM: C[M,N] = A[M,K] * B[N,K]^T + bias -----------------
// mode 0: A = hidden_states, scatter into g_q/g_k/g_v (qkv layout)
// mode 1: A = g_attn (internal), write C = d_out
__global__ void gemm_nt_kernel(const float* __restrict__ A,
                               const float* __restrict__ B,
                               const float* __restrict__ bias,
                               float* __restrict__ C,
                               int M, int N, int K, int mode)
{
    __shared__ float As[16][68];
    __shared__ float Bs[16][68];
    const float* Ap = (mode == 0) ? A : g_attn;

    int t  = threadIdx.x;          // 256 threads
    int tx = t & 15, ty = t >> 4;
    int r0 = blockIdx.y * 64, c0 = blockIdx.x * 64;

    float acc[4][4] = {};

    for (int k0 = 0; k0 < K; k0 += 16) {
        #pragma unroll
        for (int i = 0; i < 4; i++) {
            int e = t + i * 256;
            int r = e >> 4, kk = e & 15;
            As[kk][r] = Ap[(size_t)(r0 + r) * K + k0 + kk];
            Bs[kk][r] = B [(size_t)(c0 + r) * K + k0 + kk];
        }
        __syncthreads();
        #pragma unroll
        for (int kk = 0; kk < 16; kk++) {
            float a[4], b[4];
            #pragma unroll
            for (int i = 0; i < 4; i++) a[i] = As[kk][ty * 4 + i];
            #pragma unroll
            for (int j = 0; j < 4; j++) b[j] = Bs[kk][tx * 4 + j];
            #pragma unroll
            for (int i = 0; i < 4; i++)
                #pragma unroll
                for (int j = 0; j < 4; j++)
                    acc[i][j] = fmaf(a[i], b[j], acc[i][j]);
        }
        __syncthreads();
    }

    #pragma unroll
    for (int i = 0; i < 4; i++) {
        int row = r0 + ty * 4 + i;
        #pragma unroll
        for (int j = 0; j < 4; j++) {
            int col = c0 + tx * 4 + j;
            float v = acc[i][j] + bias[col];
            if (mode == 0) {
                int which = col / EMB;           // 0=q 1=k 2=v
                int rem   = col - which * EMB;
                int h = rem / HD, d = rem - h * HD;
                float* dst = (which == 0) ? g_q : (which == 1) ? g_k : g_v;
                dst[((size_t)h * SEQ + row) * HD + d] = v;
            } else {
                C[(size_t)row * N + col] = v;
            }
        }
    }
}

// ---------------- RoPE in place on g_q, g_k ----------------
__global__ void rope_kernel(const float* __restrict__ cosb,
                            const float* __restrict__ sinb)
{
    int idx = blockIdx.x * blockDim.x + threadIdx.x;   // NH*SEQ*40
    if (idx >= NH * SEQ * (HD / 2)) return;
    int d = idx % 40;
    int s = (idx / 40) % SEQ;
    int h = idx / (40 * SEQ);
    float c1 = cosb[s * HD + d],      s1 = sinb[s * HD + d];
    float c2 = cosb[s * HD + d + 40], s2 = sinb[s * HD + d + 40];
    size_t base = ((size_t)h * SEQ + s) * HD;
    float q1 = g_q[base + d], q2 = g_q[base + d + 40];
    g_q[base + d]      = q1 * c1 - q2 * s1;
    g_q[base + d + 40] = q2 * c2 + q1 * s2;
    float k1 = g_k[base + d], k2 = g_k[base + d + 40];
    g_k[base + d]      = k1 * c1 - k2 * s1;
    g_k[base + d + 40] = k2 * c2 + k1 * s2;
}

// ---------------- Flash attention, block-diagonal segments ----------------
// grid: (SEQ/64, NH). block: 256 threads. dynamic smem ~58.9 KB.
#define FLASH_SMEM_FLOATS (64 * 81 * 2 + 64 * 65 + 3 * 64)

__global__ void flash_kernel(const int* __restrict__ cu, int ncu)
{
    extern __shared__ float sh[];
    float* Qs   = sh;                  // 64 x 81
    float* KVs  = Qs + 64 * 81;        // 64 x 81 (K, then reused for V)
    float* Ss   = KVs + 64 * 81;       // 64 x 65 (scores / probs)
    float* mrow = Ss + 64 * 65;        // 64
    float* lrow = mrow + 64;           // 64
    float* crow = lrow + 64;           // 64

    int t  = threadIdx.x;
    int tx = t & 15, ty = t >> 4;
    int h   = blockIdx.y;
    int qr0 = blockIdx.x * 64;

    const float* gq = g_q + ((size_t)h * SEQ + qr0) * HD;
    const float* gk = g_k + (size_t)h * SEQ * HD;
    const float* gv = g_v + (size_t)h * SEQ * HD;

    // load Q tile (pre-scaled by sqrt(80))
    for (int e = t; e < 64 * HD; e += 256) {
        int r = e / HD, d = e - r * HD;
        Qs[r * 81 + d] = gq[r * HD + d] * QKSCALE;
    }
    if (t < 64) { mrow[t] = -INFINITY; lrow[t] = 0.f; }

    // segment bounds for this q tile (block-diagonal mask)
    int s0 = 0, s1 = SEQ;
    for (int i = 0; i < ncu - 1; i++) {
        if (cu[i] <= qr0 && qr0 < cu[i + 1]) { s0 = cu[i]; s1 = cu[i + 1]; break; }
    }

    // output accumulator: rows ty*4+i (4), cols tx*5+j (5)
    float acc[4][5];
    #pragma unroll
    for (int i = 0; i < 4; i++)
        #pragma unroll
        for (int j = 0; j < 5; j++) acc[i][j] = 0.f;

    __syncthreads();

    for (int kt = s0; kt < s1; kt += 64) {
        int kn = min(64, s1 - kt);

        // load K tile
        for (int e = t; e < 64 * HD; e += 256) {
            int c = e / HD, d = e - c * HD;
            KVs[c * 81 + d] = (c < kn) ? gk[(size_t)(kt + c) * HD + d] : 0.f;
        }
        __syncthreads();

        // S = Q K^T  (16x16 threads, 4x4 each)
        float sacc[4][4] = {};
        #pragma unroll 8
        for (int kk = 0; kk < HD; kk++) {
            float a[4], b[4];
            #pragma unroll
            for (int i = 0; i < 4; i++) a[i] = Qs[(ty * 4 + i) * 81 + kk];
            #pragma unroll
            for (int j = 0; j < 4; j++) b[j] = KVs[(tx * 4 + j) * 81 + kk];
            #pragma unroll
            for (int i = 0; i < 4; i++)
                #pragma unroll
                for (int j = 0; j < 4; j++)
                    sacc[i][j] = fmaf(a[i], b[j], sacc[i][j]);
        }
        #pragma unroll
        for (int i = 0; i < 4; i++)
            #pragma unroll
            for (int j = 0; j < 4; j++) {
                int c = tx * 4 + j;
                Ss[(ty * 4 + i) * 65 + c] = (c < kn) ? sacc[i][j] : -INFINITY;
            }
        __syncthreads();

        // online softmax row update (64 threads)
        if (t < 64) {
            int r = t;
            float mo = mrow[r];
            float mx = mo;
            #pragma unroll 8
            for (int c = 0; c < 64; c++) mx = fmaxf(mx, Ss[r * 65 + c]);
            float corr = expf(mo - mx);            // exp(-inf)=0 on first tile
            float sum = 0.f;
            #pragma unroll 8
            for (int c = 0; c < 64; c++) {
                float p = expf(Ss[r * 65 + c] - mx);
                Ss[r * 65 + c] = p;
                sum += p;
            }
            mrow[r] = mx;
            lrow[r] = lrow[r] * corr + sum;
            crow[r] = corr;
        }
        __syncthreads();

        // rescale accumulators, then load V into the K buffer
        #pragma unroll
        for (int i = 0; i < 4; i++) {
            float cf = crow[ty * 4 + i];
            #pragma unroll
            for (int j = 0; j < 5; j++) acc[i][j] *= cf;
        }
        for (int e = t; e < 64 * HD; e += 256) {
            int c = e / HD, d = e - c * HD;
            KVs[c * 81 + d] = (c < kn) ? gv[(size_t)(kt + c) * HD + d] : 0.f;
        }
        __syncthreads();

        // O += P V  (rows ty*4+i, cols tx*5+j)
        #pragma unroll 4
        for (int kk = 0; kk < 64; kk++) {
            float a[4], b[5];
            #pragma unroll
            for (int i = 0; i < 4; i++) a[i] = Ss[(ty * 4 + i) * 65 + kk];
            #pragma unroll
            for (int j = 0; j < 5; j++) b[j] = KVs[kk * 81 + tx * 5 + j];
            #pragma unroll
            for (int i = 0; i < 4; i++)
                #pragma unroll
                for (int j = 0; j < 5; j++)
                    acc[i][j] = fmaf(a[i], b[j], acc[i][j]);
        }
        __syncthreads();
    }

    // normalize and write to g_attn [s][h*80 + d]
    #pragma unroll
    for (int i = 0; i < 4; i++) {
        int r = ty * 4 + i;
        float inv = 1.f / lrow[r];
        float* dst = g_attn + (size_t)(qr0 + r) * EMB + h * HD + tx * 5;
        #pragma unroll
        for (int j = 0; j < 5; j++) dst[j] = acc[i][j] * inv;
    }
}

// ---------------- launch ----------------
extern "C" void kernel_launch(void* const* d_in, const int* in_sizes, int n_in,
                              void* d_out, int out_size)
{
    const float* hs     = (const float*)d_in[0];
    const float* w_qkv  = (const float*)d_in[1];
    const float* b_qkv  = (const float*)d_in[2];
    const float* w_proj = (const float*)d_in[3];
    const float* b_proj = (const float*)d_in[4];
    const float* cosb   = (const float*)d_in[5];
    const float* sinb   = (const float*)d_in[6];
    const int*   cu     = (const int*)d_in[7];
    int ncu = in_sizes[7];
    float* out = (float*)d_out;

    cudaFuncSetAttribute(flash_kernel, cudaFuncAttributeMaxDynamicSharedMemorySize,
                         FLASH_SMEM_FLOATS * (int)sizeof(float));

    // 1) QKV GEMM + bias, scattered into per-head q/k/v
    dim3 g1(3 * EMB / 64, SEQ / 64);
    gemm_nt_kernel<<<g1, 256>>>(hs, w_qkv, b_qkv, nullptr, SEQ, 3 * EMB, EMB, 0);

    // 2) RoPE on q, k
    int nrope = NH * SEQ * (HD / 2);
    rope_kernel<<<(nrope + 255) / 256, 256>>>(cosb, sinb);

    // 3) block-diagonal flash attention
    dim3 gf(SEQ / 64, NH);
    flash_kernel<<<gf, 256, FLASH_SMEM_FLOATS * (int)sizeof(float)>>>(cu, ncu);

    // 4) output projection + bias
    dim3 g2(EMB / 64, SEQ / 64);
    gemm_nt_kernel<<<g2, 256>>>(nullptr, w_proj, b_proj, out, SEQ, EMB, EMB, 1);
}

// round 3
// speedup vs baseline: 2.2429x; 2.2429x over previous
#include <cuda_runtime.h>
#include <cuda_bf16.h>
#include <cstdint>
#include <math.h>

#define SEQ 4096
#define EMB 1280
#define NH 16
#define HD 80
#define QKSCALE 8.94427190999915878564f  // sqrt(80) — reference MULTIPLIES by sqrt(head_dim)

// ---------------- device scratch (no allocations allowed) ----------------
__device__ float g_q[NH * SEQ * HD];
__device__ float g_k[NH * SEQ * HD];
__device__ float g_v[NH * SEQ * HD];
__device__ float g_attn[SEQ * EMB];
__device__ __align__(16) __nv_bfloat16 g_ah[SEQ * EMB];       // A hi (hidden / attn)
__device__ __align__(16) __nv_bfloat16 g_al[SEQ * EMB];       // A lo
__device__ __align__(16) __nv_bfloat16 g_bh[3 * EMB * EMB];   // B hi (w_qkv / w_proj)
__device__ __align__(16) __nv_bfloat16 g_bl[3 * EMB * EMB];   // B lo

// ---------------- mma.sync + cp.async helpers (compute_103-safe) ----------------
__device__ __forceinline__ void mma_bf16(float* d, const uint32_t* a, const uint32_t* b) {
    asm volatile(
        "mma.sync.aligned.m16n8k16.row.col.f32.bf16.bf16.f32 "
        "{%0,%1,%2,%3}, {%4,%5,%6,%7}, {%8,%9}, {%0,%1,%2,%3};\n"
        : "+f"(d[0]), "+f"(d[1]), "+f"(d[2]), "+f"(d[3])
        : "r"(a[0]), "r"(a[1]), "r"(a[2]), "r"(a[3]), "r"(b[0]), "r"(b[1]));
}
__device__ __forceinline__ uint32_t smem_u32(const void* p) {
    uint32_t a;
    asm("{ .reg .u64 t; cvta.to.shared.u64 t, %1; cvt.u32.u64 %0, t; }" : "=r"(a) : "l"(p));
    return a;
}
__device__ __forceinline__ void cp_async16(uint32_t s, const void* g) {
    asm volatile("cp.async.cg.shared.global [%0], [%1], 16;\n" :: "r"(s), "l"(g));
}
#define CP_COMMIT() asm volatile("cp.async.commit_group;\n" ::: "memory")
#define CP_WAIT1()  asm volatile("cp.async.wait_group 1;\n" ::: "memory")

// ---------------- fp32 -> bf16 hi/lo split ----------------
__global__ void split_kernel(const float* __restrict__ x,
                             __nv_bfloat16* __restrict__ hi,
                             __nv_bfloat16* __restrict__ lo, int n4)
{
    int i = blockIdx.x * 256 + threadIdx.x;
    if (i >= n4) return;
    float4 v = reinterpret_cast<const float4*>(x)[i];
    __nv_bfloat16 h0 = __float2bfloat16(v.x);
    __nv_bfloat16 h1 = __float2bfloat16(v.y);
    __nv_bfloat16 h2 = __float2bfloat16(v.z);
    __nv_bfloat16 h3 = __float2bfloat16(v.w);
    __nv_bfloat162* hp = reinterpret_cast<__nv_bfloat162*>(hi);
    __nv_bfloat162* lp = reinterpret_cast<__nv_bfloat162*>(lo);
    hp[2 * i]     = __nv_bfloat162{h0, h1};
    hp[2 * i + 1] = __nv_bfloat162{h2, h3};
    lp[2 * i]     = __nv_bfloat162{__float2bfloat16(v.x - __bfloat162float(h0)),
                                   __float2bfloat16(v.y - __bfloat162float(h1))};
    lp[2 * i + 1] = __nv_bfloat162{__float2bfloat16(v.z - __bfloat162float(h2)),
                                   __float2bfloat16(v.w - __bfloat162float(h3))};
}

// ---------------- HMMA split-bf16 GEMM: C[M,N] = A*B^T + bias ----------------
// CTA 128x128, K-chunk 32, 8 warps (warp tile 64x32). cp.async double buffer.
// smem tile layout: [128 rows][40 bf16] (80B row stride, conflict-free frags).
#define GPAD   40
#define TILE_B (128 * GPAD * 2)      // 10240 B
#define BUF_B  (4 * TILE_B)          // 40960 B (Ah, Al, Bh, Bl)
#define GEMM_SMEM (2 * BUF_B)        // 81920 B

__global__ __launch_bounds__(256, 2) void gemm_tc_kernel(
    const __nv_bfloat16* __restrict__ Ah, const __nv_bfloat16* __restrict__ Al,
    const __nv_bfloat16* __restrict__ Bh, const __nv_bfloat16* __restrict__ Bl,
    const float* __restrict__ bias, float* __restrict__ C, int K, int mode)
{
    extern __shared__ char smem[];
    uint32_t sb = smem_u32(smem);

    int t = threadIdx.x, lane = t & 31, wid = t >> 5;
    int wm = wid >> 2, wn = wid & 3;              // warp tile: rows wm*64, cols wn*32
    int c0 = blockIdx.x * 128, r0 = blockIdx.y * 128;

    const __nv_bfloat16* src[4] = {Ah + (size_t)r0 * K, Al + (size_t)r0 * K,
                                   Bh + (size_t)c0 * K, Bl + (size_t)c0 * K};

    auto load_chunk = [&](int p, int k0) {
        #pragma unroll
        for (int m = 0; m < 4; m++) {
            #pragma unroll
            for (int i = 0; i < 2; i++) {
                int e = t + i * 256;
                int row = e >> 2, col = e & 3;
                cp_async16(sb + p * BUF_B + m * TILE_B + row * (GPAD * 2) + col * 16,
                           src[m] + (size_t)row * K + k0 + col * 8);
            }
        }
    };

    float acc[4][4][4];
    #pragma unroll
    for (int a = 0; a < 4; a++)
        #pragma unroll
        for (int b = 0; b < 4; b++)
            #pragma unroll
            for (int c = 0; c < 4; c++) acc[a][b][c] = 0.f;

    int r = lane >> 2, cq = lane & 3;
    int nch = K / 32;

    load_chunk(0, 0);
    CP_COMMIT();

    for (int c = 0; c < nch; c++) {
        int p = c & 1;
        if (c + 1 < nch) load_chunk(1 - p, (c + 1) * 32);
        CP_COMMIT();
        CP_WAIT1();
        __syncthreads();

        const char* buf = smem + p * BUF_B;
        const char* tAh = buf;
        const char* tAl = buf + TILE_B;
        const char* tBh = buf + 2 * TILE_B;
        const char* tBl = buf + 3 * TILE_B;

        #pragma unroll
        for (int ks = 0; ks < 32; ks += 16) {
            int kb = (ks + cq * 2) * 2;          // byte offset of this lane's k pair
            uint32_t ah[4][4], bh[4][2];
            #pragma unroll
            for (int mf = 0; mf < 4; mf++) {
                int row0 = wm * 64 + mf * 16 + r;
                ah[mf][0] = *(const uint32_t*)(tAh + row0 * 80 + kb);
                ah[mf][1] = *(const uint32_t*)(tAh + (row0 + 8) * 80 + kb);
                ah[mf][2] = *(const uint32_t*)(tAh + row0 * 80 + kb + 16);
                ah[mf][3] = *(const uint32_t*)(tAh + (row0 + 8) * 80 + kb + 16);
            }
            #pragma unroll
            for (int nf = 0; nf < 4; nf++) {
                int n0 = wn * 32 + nf * 8 + r;
                bh[nf][0] = *(const uint32_t*)(tBh + n0 * 80 + kb);
                bh[nf][1] = *(const uint32_t*)(tBh + n0 * 80 + kb + 16);
            }
            #pragma unroll
            for (int mf = 0; mf < 4; mf++)
                #pragma unroll
                for (int nf = 0; nf < 4; nf++)
                    mma_bf16(acc[mf][nf], ah[mf], bh[nf]);

            uint32_t bl[4][2];
            #pragma unroll
            for (int nf = 0; nf < 4; nf++) {
                int n0 = wn * 32 + nf * 8 + r;
                bl[nf][0] = *(const uint32_t*)(tBl + n0 * 80 + kb);
                bl[nf][1] = *(const uint32_t*)(tBl + n0 * 80 + kb + 16);
            }
            #pragma unroll
            for (int mf = 0; mf < 4; mf++)
                #pragma unroll
                for (int nf = 0; nf < 4; nf++)
                    mma_bf16(acc[mf][nf], ah[mf], bl[nf]);

            uint32_t al[4][4];
            #pragma unroll
            for (int mf = 0; mf < 4; mf++) {
                int row0 = wm * 64 + mf * 16 + r;
                al[mf][0] = *(const uint32_t*)(tAl + row0 * 80 + kb);
                al[mf][1] = *(const uint32_t*)(tAl + (row0 + 8) * 80 + kb);
                al[mf][2] = *(const uint32_t*)(tAl + row0 * 80 + kb + 16);
                al[mf][3] = *(const uint32_t*)(tAl + (row0 + 8) * 80 + kb + 16);
            }
            #pragma unroll
            for (int mf = 0; mf < 4; mf++)
                #pragma unroll
                for (int nf = 0; nf < 4; nf++)
                    mma_bf16(acc[mf][nf], al[mf], bh[nf]);
        }
        __syncthreads();
    }

    // epilogue
    #pragma unroll
    for (int mf = 0; mf < 4; mf++) {
        #pragma unroll
        for (int nf = 0; nf < 4; nf++) {
            #pragma unroll
            for (int half = 0; half < 2; half++) {
                int row = r0 + wm * 64 + mf * 16 + r + half * 8;
                int col = c0 + wn * 32 + nf * 8 + cq * 2;
                float v0 = acc[mf][nf][half * 2 + 0] + bias[col];
                float v1 = acc[mf][nf][half * 2 + 1] + bias[col + 1];
                if (mode == 0) {
                    #pragma unroll
                    for (int j = 0; j < 2; j++) {
                        int cc = col + j;
                        float v = j ? v1 : v0;
                        int which = cc / EMB;
                        int rem = cc - which * EMB;
                        int h = rem / HD, dd = rem - h * HD;
                        float* dst = (which == 0) ? g_q : (which == 1) ? g_k : g_v;
                        dst[((size_t)h * SEQ + row) * HD + dd] = v;
                    }
                } else {
                    float2* dst = (float2*)(C + (size_t)row * EMB + col);
                    *dst = make_float2(v0, v1);
                }
            }
        }
    }
}

// ---------------- RoPE in place on g_q, g_k ----------------
__global__ void rope_kernel(const float* __restrict__ cosb,
                            const float* __restrict__ sinb)
{
    int idx = blockIdx.x * blockDim.x + threadIdx.x;
    if (idx >= NH * SEQ * (HD / 2)) return;
    int d = idx % 40;
    int s = (idx / 40) % SEQ;
    int h = idx / (40 * SEQ);
    float c1 = cosb[s * HD + d],      s1 = sinb[s * HD + d];
    float c2 = cosb[s * HD + d + 40], s2 = sinb[s * HD + d + 40];
    size_t base = ((size_t)h * SEQ + s) * HD;
    float q1 = g_q[base + d], q2 = g_q[base + d + 40];
    g_q[base + d]      = q1 * c1 - q2 * s1;
    g_q[base + d + 40] = q2 * c2 + q1 * s2;
    float k1 = g_k[base + d], k2 = g_k[base + d + 40];
    g_k[base + d]      = k1 * c1 - k2 * s1;
    g_k[base + d + 40] = k2 * c2 + k1 * s2;
}

// ---------------- Flash attention (SIMT fp32), block-diagonal ----------------
#define FLASH_SMEM_FLOATS (64 * 81 * 2 + 64 * 65 + 3 * 64)

__global__ void flash_kernel(const int* __restrict__ cu, int ncu)
{
    extern __shared__ float sh[];
    float* Qs   = sh;
    float* KVs  = Qs + 64 * 81;
    float* Ss   = KVs + 64 * 81;
    float* mrow = Ss + 64 * 65;
    float* lrow = mrow + 64;
    float* crow = lrow + 64;

    int t  = threadIdx.x;
    int tx = t & 15, ty = t >> 4;
    int h   = blockIdx.y;
    int qr0 = blockIdx.x * 64;

    const float* gq = g_q + ((size_t)h * SEQ + qr0) * HD;
    const float* gk = g_k + (size_t)h * SEQ * HD;
    const float* gv = g_v + (size_t)h * SEQ * HD;

    for (int e = t; e < 64 * HD; e += 256) {
        int r = e / HD, d = e - r * HD;
        Qs[r * 81 + d] = gq[r * HD + d] * QKSCALE;
    }
    if (t < 64) { mrow[t] = -INFINITY; lrow[t] = 0.f; }

    int s0 = 0, s1 = SEQ;
    for (int i = 0; i < ncu - 1; i++) {
        if (cu[i] <= qr0 && qr0 < cu[i + 1]) { s0 = cu[i]; s1 = cu[i + 1]; break; }
    }

    float acc[4][5];
    #pragma unroll
    for (int i = 0; i < 4; i++)
        #pragma unroll
        for (int j = 0; j < 5; j++) acc[i][j] = 0.f;

    __syncthreads();

    for (int kt = s0; kt < s1; kt += 64) {
        int kn = min(64, s1 - kt);

        for (int e = t; e < 64 * HD; e += 256) {
            int c = e / HD, d = e - c * HD;
            KVs[c * 81 + d] = (c < kn) ? gk[(size_t)(kt + c) * HD + d] : 0.f;
        }
        __syncthreads();

        float sacc[4][4] = {};
        #pragma unroll 8
        for (int kk = 0; kk < HD; kk++) {
            float a[4], b[4];
            #pragma unroll
            for (int i = 0; i < 4; i++) a[i] = Qs[(ty * 4 + i) * 81 + kk];
            #pragma unroll
            for (int j = 0; j < 4; j++) b[j] = KVs[(tx * 4 + j) * 81 + kk];
            #pragma unroll
            for (int i = 0; i < 4; i++)
                #pragma unroll
                for (int j = 0; j < 4; j++)
                    sacc[i][j] = fmaf(a[i], b[j], sacc[i][j]);
        }
        #pragma unroll
        for (int i = 0; i < 4; i++)
            #pragma unroll
            for (int j = 0; j < 4; j++) {
                int c = tx * 4 + j;
                Ss[(ty * 4 + i) * 65 + c] = (c < kn) ? sacc[i][j] : -INFINITY;
            }
        __syncthreads();

        if (t < 64) {
            int rr = t;
            float mo = mrow[rr];
            float mx = mo;
            #pragma unroll 8
            for (int c = 0; c < 64; c++) mx = fmaxf(mx, Ss[rr * 65 + c]);
            float corr = __expf(mo - mx);
            float sum = 0.f;
            #pragma unroll 8
            for (int c = 0; c < 64; c++) {
                float p = __expf(Ss[rr * 65 + c] - mx);
                Ss[rr * 65 + c] = p;
                sum += p;
            }
            mrow[rr] = mx;
            lrow[rr] = lrow[rr] * corr + sum;
            crow[rr] = corr;
        }
        __syncthreads();

        #pragma unroll
        for (int i = 0; i < 4; i++) {
            float cf = crow[ty * 4 + i];
            #pragma unroll
            for (int j = 0; j < 5; j++) acc[i][j] *= cf;
        }
        for (int e = t; e < 64 * HD; e += 256) {
            int c = e / HD, d = e - c * HD;
            KVs[c * 81 + d] = (c < kn) ? gv[(size_t)(kt + c) * HD + d] : 0.f;
        }
        __syncthreads();

        #pragma unroll 4
        for (int kk = 0; kk < 64; kk++) {
            float a[4], b[5];
            #pragma unroll
            for (int i = 0; i < 4; i++) a[i] = Ss[(ty * 4 + i) * 65 + kk];
            #pragma unroll
            for (int j = 0; j < 5; j++) b[j] = KVs[kk * 81 + tx * 5 + j];
            #pragma unroll
            for (int i = 0; i < 4; i++)
                #pragma unroll
                for (int j = 0; j < 5; j++)
                    acc[i][j] = fmaf(a[i], b[j], acc[i][j]);
        }
        __syncthreads();
    }

    #pragma unroll
    for (int i = 0; i < 4; i++) {
        int rr = ty * 4 + i;
        float inv = 1.f / lrow[rr];
        float* dst = g_attn + (size_t)(qr0 + rr) * EMB + h * HD + tx * 5;
        #pragma unroll
        for (int j = 0; j < 5; j++) dst[j] = acc[i][j] * inv;
    }
}

// ---------------- launch ----------------
extern "C" void kernel_launch(void* const* d_in, const int* in_sizes, int n_in,
                              void* d_out, int out_size)
{
    const float* hs     = (const float*)d_in[0];
    const float* w_qkv  = (const float*)d_in[1];
    const float* b_qkv  = (const float*)d_in[2];
    const float* w_proj = (const float*)d_in[3];
    const float* b_proj = (const float*)d_in[4];
    const float* cosb   = (const float*)d_in[5];
    const float* sinb   = (const float*)d_in[6];
    const int*   cu     = (const int*)d_in[7];
    int ncu = in_sizes[7];
    float* out = (float*)d_out;

    cudaFuncSetAttribute(gemm_tc_kernel, cudaFuncAttributeMaxDynamicSharedMemorySize, GEMM_SMEM);
    cudaFuncSetAttribute(flash_kernel, cudaFuncAttributeMaxDynamicSharedMemorySize,
                         FLASH_SMEM_FLOATS * (int)sizeof(float));

    __nv_bfloat16 *ah, *al, *bh, *bl;
    float *gattn;
    cudaGetSymbolAddress((void**)&ah, g_ah);
    cudaGetSymbolAddress((void**)&al, g_al);
    cudaGetSymbolAddress((void**)&bh, g_bh);
    cudaGetSymbolAddress((void**)&bl, g_bl);
    cudaGetSymbolAddress((void**)&gattn, g_attn);

    // 1) split hidden + w_qkv to bf16 hi/lo
    int nA4 = SEQ * EMB / 4, nB4 = 3 * EMB * EMB / 4;
    split_kernel<<<(nA4 + 255) / 256, 256>>>(hs, ah, al, nA4);
    split_kernel<<<(nB4 + 255) / 256, 256>>>(w_qkv, bh, bl, nB4);

    // 2) QKV GEMM (HMMA split-bf16), scatter into q/k/v
    dim3 g1(3 * EMB / 128, SEQ / 128);
    gemm_tc_kernel<<<g1, 256, GEMM_SMEM>>>(ah, al, bh, bl, b_qkv, nullptr, EMB, 0);

    // 3) RoPE
    int nrope = NH * SEQ * (HD / 2);
    rope_kernel<<<(nrope + 255) / 256, 256>>>(cosb, sinb);

    // 4) flash attention
    dim3 gf(SEQ / 64, NH);
    flash_kernel<<<gf, 256, FLASH_SMEM_FLOATS * (int)sizeof(float)>>>(cu, ncu);

    // 5) split attn + w_proj, then proj GEMM
    int nP4 = EMB * EMB / 4;
    split_kernel<<<(nA4 + 255) / 256, 256>>>(gattn, ah, al, nA4);
    split_kernel<<<(nP4 + 255) / 256, 256>>>(w_proj, bh, bl, nP4);
    dim3 g2(EMB / 128, SEQ / 128);
    gemm_tc_kernel<<<g2, 256, GEMM_SMEM>>>(ah, al, bh, bl, b_proj, out, EMB, 1);
}